// round 9
// baseline (speedup 1.0000x reference)
#include <cuda_runtime.h>
#include <cuda_bf16.h>

// -------------------- scratch (no allocations allowed) --------------------
#define CAP 262144   // >= S*B*N = 204800

__device__ int g_pos [CAP];   // pos[inst*N + node_local] = tour position
__device__ int g_winf[CAP];   // min edge idx matching forward query at (inst,pos)
__device__ int g_winr[CAP];   // min edge idx matching reverse query at (inst,pos)

#define NOTFOUND 0x7fffffff

// -------------------- input identification (uniform, cached) --------------
__device__ __forceinline__ bool is64_arange(const unsigned* p) {
    return p[0]==0u && p[1]==0u && p[2]==1u && p[3]==0u &&
           p[4]==2u && p[5]==0u && p[6]==3u && p[7]==0u;
}
__device__ __forceinline__ bool is32_arange(const unsigned* p) {
    return p[0]==0u && p[1]==1u && p[2]==2u && p[3]==3u &&
           p[4]==4u && p[5]==5u && p[6]==6u && p[7]==7u;
}
// bit0 = pb is node_offset (so pa is y), bit1 = ints are 64-bit
__device__ __forceinline__ int detect_cfg(const unsigned* pa, const unsigned* pb) {
    if (is64_arange(pa)) return 2;
    if (is32_arange(pa)) return 0;
    if (is64_arange(pb)) return 3;
    return 1;
}

// -------------------- kernel A: inverse permutation + winner init ---------
// 4 elements per thread: int4 load of y, int4 init stores, scalar pos scatter.
__global__ void prep_kernel(const unsigned* __restrict__ pa,
                            const unsigned* __restrict__ pb,
                            int total, int N) {
    int cfg = detect_cfg(pa, pb);
    const int* y = (const int*)((cfg & 1) ? pa : pb);

    int j4 = (blockIdx.x * blockDim.x + threadIdx.x) * 4;
    if (j4 >= total) return;
    const int NF = NOTFOUND;

    if (j4 + 4 <= total) {
        int4 yv = *(const int4*)(y + j4);
        int inst0 = j4 / N;                 // N>=4 assumed; handle straddle below
        int i0 = j4 - inst0 * N;
        // element-wise (instance may change mid-vector)
        int idx, inst, i;
        inst = inst0; i = i0;
        idx = inst * N + yv.x; g_pos[idx] = i;
        if (++i == N) { i = 0; inst++; }
        idx = inst * N + yv.y; g_pos[idx] = i;
        if (++i == N) { i = 0; inst++; }
        idx = inst * N + yv.z; g_pos[idx] = i;
        if (++i == N) { i = 0; inst++; }
        idx = inst * N + yv.w; g_pos[idx] = i;
        int4 nf4 = make_int4(NF, NF, NF, NF);
        *(int4*)(g_winf + j4) = nf4;
        *(int4*)(g_winr + j4) = nf4;
    } else {
        for (int j = j4; j < total; j++) {
            int inst = j / N;
            int i = j - inst * N;
            g_pos[inst * N + y[j]] = i;
            g_winf[j] = NF;
            g_winr[j] = NF;
        }
    }
}

// -------------------- kernel B: scatter edges onto tour positions ---------
// 2 edges per thread; vector loads on the int64 path.
__global__ void match_kernel(const unsigned* __restrict__ pa,
                             const unsigned* __restrict__ pb,
                             const void* __restrict__ eidx,
                             int E, int N) {
    int cfg = detect_cfg(pa, pb);
    int e0 = (blockIdx.x * blockDim.x + threadIdx.x) * 2;
    if (e0 >= E) return;

    unsigned s[2], d[2];
    int cnt = (e0 + 2 <= E) ? 2 : 1;
    if (cfg & 2) {
        const long long* p = (const long long*)eidx;
        if (cnt == 2) {
            longlong2 sv = *(const longlong2*)(p + e0);
            longlong2 dv = *(const longlong2*)(p + E + e0);
            s[0] = (unsigned)sv.x; s[1] = (unsigned)sv.y;
            d[0] = (unsigned)dv.x; d[1] = (unsigned)dv.y;
        } else {
            s[0] = (unsigned)p[e0]; d[0] = (unsigned)p[E + e0];
        }
    } else {
        const int* p = (const int*)eidx;
        if (cnt == 2) {
            int2 sv = *(const int2*)(p + e0);
            int2 dv = *(const int2*)(p + E + e0);
            s[0] = (unsigned)sv.x; s[1] = (unsigned)sv.y;
            d[0] = (unsigned)dv.x; d[1] = (unsigned)dv.y;
        } else {
            s[0] = (unsigned)p[e0]; d[0] = (unsigned)p[E + e0];
        }
    }

    unsigned uN = (unsigned)N;
    #pragma unroll
    for (int k = 0; k < 2; k++) {
        if (k >= cnt) break;
        int e = e0 + k;
        unsigned is = s[k] / uN;
        unsigned id = d[k] / uN;
        if (is != id) continue;               // cross-instance: can't match
        unsigned sl = s[k] - is * uN;
        unsigned dl = d[k] - id * uN;
        int base = (int)is * N;
        int ps = g_pos[base + sl];
        int pd = g_pos[base + dl];
        int psn = (ps + 1 == N) ? 0 : ps + 1;
        int pdn = (pd + 1 == N) ? 0 : pd + 1;
        if (psn == pd) atomicMin(&g_winf[base + ps], e);   // forward match
        if (pdn == ps) atomicMin(&g_winr[base + pd], e);   // reverse match
    }
}

// -------------------- kernel C: gather + mean -----------------------------
// grid = S*B blocks, blockDim = 128 (4 warps). Warp w owns rows w, w+4, ...
__global__ void gather_kernel(const float* __restrict__ emb,
                              float* __restrict__ out,
                              int N, int EM) {
    __shared__ int   sidx[128];
    __shared__ float sacc[4 * 128];

    int inst = blockIdx.x;
    int t = threadIdx.x;
    int base = inst * N;

    if (t < N) {
        int vf = g_winf[base + t];
        int vr = g_winr[base + t];
        sidx[t] = (vf != NOTFOUND) ? vf : ((vr != NOTFOUND) ? vr : -1);
    }
    __syncthreads();

    if (EM == 128) {
        int w = t >> 5, l = t & 31;
        float4 acc = make_float4(0.f, 0.f, 0.f, 0.f);
        #pragma unroll 8
        for (int i = w; i < N; i += 4) {
            int v = sidx[i];
            if (v >= 0) {
                float4 x = ((const float4*)(emb + (long long)v * 128))[l];
                acc.x += x.x; acc.y += x.y; acc.z += x.z; acc.w += x.w;
            }
        }
        ((float4*)(sacc + w * 128))[l] = acc;
        __syncthreads();
        float s = sacc[t] + sacc[128 + t] + sacc[256 + t] + sacc[384 + t];
        out[(long long)inst * 128 + t] = s * (1.0f / (float)N);
    } else {
        if (t < EM) {
            float acc = 0.0f;
            for (int i = 0; i < N; i++) {
                int v = sidx[i];
                if (v >= 0) acc += emb[(long long)v * EM + t];
            }
            out[(long long)inst * EM + t] = acc * (1.0f / (float)N);
        }
    }
}

// -------------------- launcher --------------------------------------------
extern "C" void kernel_launch(void* const* d_in, const int* in_sizes, int n_in,
                              void* d_out, int out_size) {
    // Identify inputs by element count (robust to ordering):
    //   edge_emb -> largest, edge_index -> second, y/node_offset -> the pair.
    int order[16];
    for (int i = 0; i < n_in && i < 16; i++) order[i] = i;
    for (int i = 0; i < n_in; i++)
        for (int j = i + 1; j < n_in; j++)
            if (in_sizes[order[j]] > in_sizes[order[i]]) {
                int tmp = order[i]; order[i] = order[j]; order[j] = tmp;
            }
    int emb_i  = order[0];
    int eidx_i = order[1];
    int pa_i   = order[2];
    int pb_i   = order[3];

    const float*    emb  = (const float*)d_in[emb_i];
    const void*     eidx = d_in[eidx_i];
    const unsigned* pa   = (const unsigned*)d_in[pa_i];
    const unsigned* pb   = (const unsigned*)d_in[pb_i];
    float*          out  = (float*)d_out;

    int total = in_sizes[pa_i];                    // S*B*N
    int E  = in_sizes[eidx_i] / 2;
    int EM = in_sizes[emb_i] / E;                  // 128
    int inst = out_size / EM;                      // S*B
    int N = total / inst;                          // 100

    int pt = (total + 3) / 4;
    prep_kernel <<<(pt + 255) / 256, 256>>>(pa, pb, total, N);
    int mt = (E + 1) / 2;
    match_kernel<<<(mt + 255) / 256, 256>>>(pa, pb, eidx, E, N);
    gather_kernel<<<inst, 128>>>(emb, out, N, EM);
}

// round 10
// speedup vs baseline: 1.0487x; 1.0487x over previous
#include <cuda_runtime.h>
#include <cuda_bf16.h>

// -------------------- scratch (no allocations allowed) --------------------
#define CAP 262144   // >= S*B*N = 204800

__device__ int g_pos [CAP];   // pos[inst*N + node_local] = tour position
__device__ int g_winf[CAP];   // min edge idx matching forward query at (inst,pos)
__device__ int g_winr[CAP];   // min edge idx matching reverse query at (inst,pos)

// byte-memset-friendly sentinel: memset(0x7f) => 0x7f7f7f7f; all real edge
// indices (< E ~ 4.1e5) are far below it, so atomicMin semantics hold.
#define NOTFOUND 0x7f7f7f7f

// -------------------- input identification (uniform, cached) --------------
__device__ __forceinline__ bool is64_arange(const unsigned* p) {
    return p[0]==0u && p[1]==0u && p[2]==1u && p[3]==0u &&
           p[4]==2u && p[5]==0u && p[6]==3u && p[7]==0u;
}
__device__ __forceinline__ bool is32_arange(const unsigned* p) {
    return p[0]==0u && p[1]==1u && p[2]==2u && p[3]==3u &&
           p[4]==4u && p[5]==5u && p[6]==6u && p[7]==7u;
}
// bit0 = pb is node_offset (so pa is y), bit1 = ints are 64-bit
__device__ __forceinline__ int detect_cfg(const unsigned* pa, const unsigned* pb) {
    if (is64_arange(pa)) return 2;
    if (is32_arange(pa)) return 0;
    if (is64_arange(pb)) return 3;
    return 1;
}

// -------------------- kernel A: inverse permutation ------------------------
// 1 element/thread (latency-bound: keep thread count high).
__global__ void prep_kernel(const unsigned* __restrict__ pa,
                            const unsigned* __restrict__ pb,
                            int total, int N) {
    int cfg = detect_cfg(pa, pb);
    const int* y = (const int*)((cfg & 1) ? pa : pb);

    int j = blockIdx.x * blockDim.x + threadIdx.x;
    if (j >= total) return;
    int inst = j / N;
    int i    = j - inst * N;
    g_pos[inst * N + y[j]] = i;
}

// -------------------- kernel B: scatter edges onto tour positions ---------
__global__ void match_kernel(const unsigned* __restrict__ pa,
                             const unsigned* __restrict__ pb,
                             const void* __restrict__ eidx,
                             int E, int N) {
    int cfg = detect_cfg(pa, pb);
    int e = blockIdx.x * blockDim.x + threadIdx.x;
    if (e >= E) return;

    unsigned s, d;
    if (cfg & 2) {
        const long long* p = (const long long*)eidx;
        s = (unsigned)p[e]; d = (unsigned)p[e + E];
    } else {
        const int* p = (const int*)eidx;
        s = (unsigned)p[e]; d = (unsigned)p[e + E];
    }
    unsigned uN = (unsigned)N;
    unsigned is = s / uN;
    unsigned id = d / uN;
    if (is != id) return;                 // cross-instance edge: can't match
    unsigned sl = s - is * uN;
    unsigned dl = d - id * uN;
    int base = (int)is * N;
    int ps = g_pos[base + sl];
    int pd = g_pos[base + dl];
    int psn = (ps + 1 == N) ? 0 : ps + 1;
    int pdn = (pd + 1 == N) ? 0 : pd + 1;
    if (psn == pd) atomicMin(&g_winf[base + ps], e);  // forward match at pos ps
    if (pdn == ps) atomicMin(&g_winr[base + pd], e);  // reverse match at pos pd
}

// -------------------- kernel C: gather + mean -----------------------------
// grid = S*B blocks, blockDim = 128 (4 warps). Warp w owns rows w, w+4, ...
__global__ void gather_kernel(const float* __restrict__ emb,
                              float* __restrict__ out,
                              int N, int EM) {
    __shared__ int   sidx[128];
    __shared__ float sacc[4 * 128];

    int inst = blockIdx.x;
    int t = threadIdx.x;
    int base = inst * N;

    if (t < N) {
        int vf = g_winf[base + t];
        int vr = g_winr[base + t];
        sidx[t] = (vf != NOTFOUND) ? vf : ((vr != NOTFOUND) ? vr : -1);
    }
    __syncthreads();

    if (EM == 128) {
        int w = t >> 5, l = t & 31;
        float4 acc = make_float4(0.f, 0.f, 0.f, 0.f);
        #pragma unroll 8
        for (int i = w; i < N; i += 4) {
            int v = sidx[i];
            if (v >= 0) {
                float4 x = ((const float4*)(emb + (long long)v * 128))[l];
                acc.x += x.x; acc.y += x.y; acc.z += x.z; acc.w += x.w;
            }
        }
        ((float4*)(sacc + w * 128))[l] = acc;
        __syncthreads();
        float s = sacc[t] + sacc[128 + t] + sacc[256 + t] + sacc[384 + t];
        out[(long long)inst * 128 + t] = s * (1.0f / (float)N);
    } else {
        if (t < EM) {
            float acc = 0.0f;
            for (int i = 0; i < N; i++) {
                int v = sidx[i];
                if (v >= 0) acc += emb[(long long)v * EM + t];
            }
            out[(long long)inst * EM + t] = acc * (1.0f / (float)N);
        }
    }
}

// -------------------- launcher --------------------------------------------
extern "C" void kernel_launch(void* const* d_in, const int* in_sizes, int n_in,
                              void* d_out, int out_size) {
    // Identify inputs by element count (robust to ordering):
    //   edge_emb -> largest, edge_index -> second, y/node_offset -> the pair.
    int order[16];
    for (int i = 0; i < n_in && i < 16; i++) order[i] = i;
    for (int i = 0; i < n_in; i++)
        for (int j = i + 1; j < n_in; j++)
            if (in_sizes[order[j]] > in_sizes[order[i]]) {
                int tmp = order[i]; order[i] = order[j]; order[j] = tmp;
            }
    int emb_i  = order[0];
    int eidx_i = order[1];
    int pa_i   = order[2];
    int pb_i   = order[3];

    const float*    emb  = (const float*)d_in[emb_i];
    const void*     eidx = d_in[eidx_i];
    const unsigned* pa   = (const unsigned*)d_in[pa_i];
    const unsigned* pb   = (const unsigned*)d_in[pb_i];
    float*          out  = (float*)d_out;

    int total = in_sizes[pa_i];                    // S*B*N
    int E  = in_sizes[eidx_i] / 2;
    int EM = in_sizes[emb_i] / E;                  // 128
    int inst = out_size / EM;                      // S*B
    int N = total / inst;                          // 100

    // winner-array init as graph-capturable memset nodes (0x7f bytes)
    void* winf_addr = nullptr;
    void* winr_addr = nullptr;
    cudaGetSymbolAddress(&winf_addr, g_winf);
    cudaGetSymbolAddress(&winr_addr, g_winr);
    cudaMemsetAsync(winf_addr, 0x7f, (size_t)total * sizeof(int));
    cudaMemsetAsync(winr_addr, 0x7f, (size_t)total * sizeof(int));

    prep_kernel <<<(total + 255) / 256, 256>>>(pa, pb, total, N);
    match_kernel<<<(E + 255) / 256, 256>>>(pa, pb, eidx, E, N);
    gather_kernel<<<inst, 128>>>(emb, out, N, EM);
}